// round 5
// baseline (speedup 1.0000x reference)
#include <cuda_runtime.h>

// Problem constants (match reference_code)
#define B_ 16
#define T_ 14
#define F_ 2048
#define NTF (T_ * F_)     // 28672
#define NRE (B_ * NTF)    // 458752

typedef unsigned long long ull;

// ================= packed f32x2 primitives (sm_100+ PTX only) =================
__device__ __forceinline__ ull padd(ull a, ull b) {
    ull r; asm("add.rn.f32x2 %0,%1,%2;" : "=l"(r) : "l"(a), "l"(b)); return r;
}
__device__ __forceinline__ ull psub(ull a, ull b) {
    ull r; asm("sub.rn.f32x2 %0,%1,%2;" : "=l"(r) : "l"(a), "l"(b)); return r;
}
__device__ __forceinline__ ull pmul(ull a, ull b) {
    ull r; asm("mul.rn.f32x2 %0,%1,%2;" : "=l"(r) : "l"(a), "l"(b)); return r;
}
__device__ __forceinline__ ull pfma(ull a, ull b, ull c) {
    ull r; asm("fma.rn.f32x2 %0,%1,%2,%3;" : "=l"(r) : "l"(a), "l"(b), "l"(c)); return r;
}
__device__ __forceinline__ ull pk(float lo, float hi) {
    ull r;
    asm("mov.b64 %0,{%1,%2};" : "=l"(r) : "r"(__float_as_uint(lo)), "r"(__float_as_uint(hi)));
    return r;
}
__device__ __forceinline__ void upk(ull v, float& lo, float& hi) {
    unsigned ul, uh;
    asm("mov.b64 {%0,%1},%2;" : "=r"(ul), "=r"(uh) : "l"(v));
    lo = __uint_as_float(ul); hi = __uint_as_float(uh);
}
__device__ __forceinline__ ull prsqrt(ull v) {
    float lo, hi; upk(v, lo, hi);
    return pk(rsqrtf(lo), rsqrtf(hi));
}
__device__ __forceinline__ ull prcp(ull v) {
    float lo, hi; upk(v, lo, hi);
    return pk(__fdividef(1.0f, lo), __fdividef(1.0f, hi));
}

// ================= packed complex (each component is a {f,f+1} pair) =========
struct c2 { ull re, im; };

__device__ __forceinline__ c2 cscale2(c2 a, ull s) { return {pmul(a.re, s), pmul(a.im, s)}; }
__device__ __forceinline__ ull cabs2_2(c2 a) { return pfma(a.im, a.im, pmul(a.re, a.re)); }
// a - b*c
__device__ __forceinline__ c2 csub_mul(c2 a, c2 b, c2 c) {
    ull re = pfma(b.im, c.im, psub(a.re, pmul(b.re, c.re)));
    ull im = psub(psub(a.im, pmul(b.re, c.im)), pmul(b.im, c.re));
    return {re, im};
}
// a - b*conj(c)
__device__ __forceinline__ c2 csub_mulc(c2 a, c2 b, c2 c) {
    ull re = psub(a.re, pfma(b.re, c.re, pmul(b.im, c.im)));
    ull im = pfma(b.re, c.im, psub(a.im, pmul(b.im, c.re)));
    return {re, im};
}

// ======= per-pipeline tail: reverse Cholesky + solve + SIC (all O(1)) ========
struct TailOut { c2 x0, x1, x2, x3; ull ne0, ne1, ne2, ne3; };

__device__ __forceinline__ TailOut tail_solve(
    ull Gd0, ull Gd1, ull Gd2, ull Gd3,
    c2 G01, c2 G02, c2 G03, c2 G12, c2 G13, c2 G23,
    c2 z0, c2 z1, c2 z2, c2 z3, ull no2)
{
    const ull ONE2 = 0x3F8000003F800000ULL; // {1.f, 1.f}

    // reverse Cholesky: A = G + no*I = U U^H (U upper). Nested property:
    // A[k:,k:] = U[k:,k:] U[k:,k:]^H for all k -> ONE factorization serves all
    // 4 SIC steps, and (A_k^{-1})_00 = dinv[k]^2.
    ull dinv3 = prsqrt(padd(Gd3, no2));
    c2 U23 = cscale2(G23, dinv3);
    c2 U13 = cscale2(G13, dinv3);
    c2 U03 = cscale2(G03, dinv3);

    ull dinv2 = prsqrt(psub(padd(Gd2, no2), cabs2_2(U23)));
    c2 U12 = cscale2(csub_mulc(G12, U13, U23), dinv2);
    c2 U02 = cscale2(csub_mulc(G02, U03, U23), dinv2);

    ull dinv1 = prsqrt(psub(psub(padd(Gd1, no2), cabs2_2(U12)), cabs2_2(U13)));
    c2 U01 = cscale2(csub_mulc(csub_mulc(G01, U02, U12), U03, U13), dinv1);

    ull dinv0 = prsqrt(psub(psub(psub(padd(Gd0, no2), cabs2_2(U01)), cabs2_2(U02)), cabs2_2(U03)));

    // one backward solve: w = U^{-1} z
    c2 w3 = cscale2(z3, dinv3);
    c2 w2 = cscale2(csub_mul(z2, U23, w3), dinv2);
    c2 w1 = cscale2(csub_mul(csub_mul(z1, U12, w2), U13, w3), dinv1);
    c2 w0 = cscale2(csub_mul(csub_mul(csub_mul(z0, U01, w1), U02, w2), U03, w3), dinv0);

    TailOut o;
    {   // k = 0
        ull noa = pmul(no2, pmul(dinv0, dinv0));
        ull idk = prcp(psub(ONE2, noa));
        c2 xk = cscale2(w0, pmul(dinv0, idk));
        o.x0 = xk; o.ne0 = pmul(noa, idk);
        w1 = csub_mulc(w1, xk, U01);
        w2 = csub_mulc(w2, xk, U02);
        w3 = csub_mulc(w3, xk, U03);
    }
    {   // k = 1
        ull noa = pmul(no2, pmul(dinv1, dinv1));
        ull idk = prcp(psub(ONE2, noa));
        c2 xk = cscale2(w1, pmul(dinv1, idk));
        o.x1 = xk; o.ne1 = pmul(noa, idk);
        w2 = csub_mulc(w2, xk, U12);
        w3 = csub_mulc(w3, xk, U13);
    }
    {   // k = 2
        ull noa = pmul(no2, pmul(dinv2, dinv2));
        ull idk = prcp(psub(ONE2, noa));
        c2 xk = cscale2(w2, pmul(dinv2, idk));
        o.x2 = xk; o.ne2 = pmul(noa, idk);
        w3 = csub_mulc(w3, xk, U23);
    }
    {   // k = 3
        ull noa = pmul(no2, pmul(dinv3, dinv3));
        ull idk = prcp(psub(ONE2, noa));
        o.x3 = cscale2(w3, pmul(dinv3, idk));
        o.ne3 = pmul(noa, idk);
    }
    return o;
}

// ================= main kernel: one thread per FOUR REs =======================
// LDG.128 loads feed two independent f32x2 pipelines (A = {f,f+1}, B = {f+2,f+3}).
// Two dependency streams per warp hide FMA/MUFU/memory latency at low occupancy.
__global__ void __launch_bounds__(128, 3)
sic_lmmse_kernel(const float* __restrict__ yre, const float* __restrict__ yim,
                 const float* __restrict__ hre, const float* __restrict__ him,
                 const int* __restrict__ mask, const float* __restrict__ nv,
                 float* __restrict__ out) {
    const int NQ = NTF / 4;  // RE quads per batch element = 7168
    int tid = blockIdx.x * blockDim.x + threadIdx.x;  // exact grid: NRE/4 threads
    int b = tid / NQ;
    int tf = (tid - b * NQ) * 4;  // multiple of 4 -> 16B-aligned accesses

    float no = nv[0];
    ull no2 = pk(no, no);
    const ull ZERO = 0ULL;

    // mask quad -> two packed floats
    int4 mi = *reinterpret_cast<const int4*>(mask + tf);
    ull m2A = pk((float)mi.x, (float)mi.y);
    ull m2B = pk((float)mi.z, (float)mi.w);

    int ybase = b * 4 * NTF + tf;
    int hbase = b * 16 * NTF + tf;

    // ---- Gram accumulators (upper tri + real diag) and matched filter z ----
    // index [q]: q=0 pipeline A (lo 8B of each LDG.128), q=1 pipeline B (hi 8B)
    ull Gd[2][4] = {};
    c2 Go[2][6] = {};   // 0:01 1:02 2:03 3:12 4:13 5:23
    c2 z[2][4] = {};

#pragma unroll
    for (int r = 0; r < 4; r++) {
        longlong2 Yr = __ldcs(reinterpret_cast<const longlong2*>(yre + ybase + r * NTF));
        longlong2 Yi = __ldcs(reinterpret_cast<const longlong2*>(yim + ybase + r * NTF));
        longlong2 Hr[4], Hi[4];
#pragma unroll
        for (int s = 0; s < 4; s++) {
            Hr[s] = __ldcs(reinterpret_cast<const longlong2*>(hre + hbase + (r * 4 + s) * NTF));
            Hi[s] = __ldcs(reinterpret_cast<const longlong2*>(him + hbase + (r * 4 + s) * NTF));
        }
#pragma unroll
        for (int q = 0; q < 2; q++) {
            ull yr = (ull)(q ? Yr.y : Yr.x);
            ull yi = (ull)(q ? Yi.y : Yi.x);
            ull hr[4], hi[4], ni[4];
#pragma unroll
            for (int s = 0; s < 4; s++) {
                hr[s] = (ull)(q ? Hr[s].y : Hr[s].x);
                hi[s] = (ull)(q ? Hi[s].y : Hi[s].x);
                ni[s] = psub(ZERO, hi[s]);  // -im keeps the conj-FMAs pure
            }

            // diagonals Gd[s] += |h_s|^2
#pragma unroll
            for (int s = 0; s < 4; s++)
                Gd[q][s] = pfma(hr[s], hr[s], pfma(hi[s], hi[s], Gd[q][s]));

            // off-diagonals G[s][u] += conj(h_s)*h_u
#define CMAC(IDX, S, U)                                                          \
            Go[q][IDX].re = pfma(hr[S], hr[U], pfma(hi[S], hi[U], Go[q][IDX].re)); \
            Go[q][IDX].im = pfma(hr[S], hi[U], pfma(ni[S], hr[U], Go[q][IDX].im));
            CMAC(0, 0, 1) CMAC(1, 0, 2) CMAC(2, 0, 3)
            CMAC(3, 1, 2) CMAC(4, 1, 3) CMAC(5, 2, 3)
#undef CMAC

            // z[s] += conj(h_s)*y
#pragma unroll
            for (int s = 0; s < 4; s++) {
                z[q][s].re = pfma(hr[s], yr, pfma(hi[s], yi, z[q][s].re));
                z[q][s].im = pfma(hr[s], yi, pfma(ni[s], yr, z[q][s].im));
            }
        }
    }

    // ---- two independent tails (ptxas interleaves them for ILP) ----
    TailOut A = tail_solve(Gd[0][0], Gd[0][1], Gd[0][2], Gd[0][3],
                           Go[0][0], Go[0][1], Go[0][2], Go[0][3], Go[0][4], Go[0][5],
                           z[0][0], z[0][1], z[0][2], z[0][3], no2);
    TailOut B = tail_solve(Gd[1][0], Gd[1][1], Gd[1][2], Gd[1][3],
                           Go[1][0], Go[1][1], Go[1][2], Go[1][3], Go[1][4], Go[1][5],
                           z[1][0], z[1][1], z[1][2], z[1][3], no2);

    // ---- merged 16B masked stores: x_ri [2,B,S,T,F] then no_eff [B,S,T,F] ----
    const int X = B_ * 4 * NTF;  // 1,835,008
    int obase = (b * 4) * NTF + tf;

#define ST16(PTR, VA, VB) {                                                  \
        longlong2 _o;                                                        \
        _o.x = (long long)pmul(VA, m2A);                                     \
        _o.y = (long long)pmul(VB, m2B);                                     \
        __stcs(reinterpret_cast<longlong2*>(PTR), _o); }

    {
        int o = obase;
        ST16(out + o,         A.x0.re, B.x0.re)
        ST16(out + X + o,     A.x0.im, B.x0.im)
        ST16(out + 2 * X + o, A.ne0,   B.ne0)
    }
    {
        int o = obase + NTF;
        ST16(out + o,         A.x1.re, B.x1.re)
        ST16(out + X + o,     A.x1.im, B.x1.im)
        ST16(out + 2 * X + o, A.ne1,   B.ne1)
    }
    {
        int o = obase + 2 * NTF;
        ST16(out + o,         A.x2.re, B.x2.re)
        ST16(out + X + o,     A.x2.im, B.x2.im)
        ST16(out + 2 * X + o, A.ne2,   B.ne2)
    }
    {
        int o = obase + 3 * NTF;
        ST16(out + o,         A.x3.re, B.x3.re)
        ST16(out + X + o,     A.x3.im, B.x3.im)
        ST16(out + 2 * X + o, A.ne3,   B.ne3)
    }
#undef ST16
}

extern "C" void kernel_launch(void* const* d_in, const int* in_sizes, int n_in,
                              void* d_out, int out_size) {
    const float* y_re = (const float*)d_in[0];
    const float* y_im = (const float*)d_in[1];
    const float* h_re = (const float*)d_in[2];
    const float* h_im = (const float*)d_in[3];
    const int* mask = (const int*)d_in[4];
    const float* noise_var = (const float*)d_in[5];
    float* out = (float*)d_out;

    const int threads = 128;
    const int blocks = (NRE / 4) / threads;  // exact: 114688 / 128 = 896
    sic_lmmse_kernel<<<blocks, threads>>>(y_re, y_im, h_re, h_im, mask, noise_var, out);
}